// round 11
// baseline (speedup 1.0000x reference)
#include <cuda_runtime.h>

typedef unsigned long long ull;

#define HW 512
#define IMG (512 * 512)

// weight layout per channel: 28 ull slots (224B, 16B-aligned), 65 channels
// (65th = zeros, prefetch overrun target)
//  slots 0..17 : 9 rows x (w0pair, w2pair)  -> ulonglong2 index 0..8
//  slots 18..26: w1pair rows 0..8           -> ulonglong2 index 9..13
//  slot  27    : pad
__constant__ ull c_wpair[65 * 28];
__device__ ull d_scratch[65 * 28];   // zero-initialized at load; prep fills first 64

__device__ __forceinline__ ull pk(float lo, float hi) {
    ull r;
    asm("mov.b64 %0, {%1,%2};" : "=l"(r) : "f"(lo), "f"(hi));
    return r;
}
__device__ __forceinline__ ull ffma2(ull a, ull b, ull c) {
    ull d;
    asm("fma.rn.f32x2 %0, %1, %2, %3;" : "=l"(d) : "l"(a), "l"(b), "l"(c));
    return d;
}
__device__ __forceinline__ ull fadd2(ull a, ull b) {
    ull d;
    asm("add.rn.f32x2 %0, %1, %2;" : "=l"(d) : "l"(a), "l"(b));
    return d;
}
// (a.hi, b.lo)
__device__ __forceinline__ ull cross(ull a, ull b) {
    ull r;
    asm("{\n\t"
        ".reg .b32 al, ah, bl, bh;\n\t"
        "mov.b64 {al, ah}, %1;\n\t"
        "mov.b64 {bl, bh}, %2;\n\t"
        "mov.b64 %0, {ah, bl};\n\t"
        "}" : "=l"(r) : "l"(a), "l"(b));
    return r;
}

__global__ void prep_weights(const float* __restrict__ wm) {
    int i = blockIdx.x * blockDim.x + threadIdx.x;   // over 64*28 slots
    if (i < 64 * 28) {
        int c = i / 28, s = i - c * 28;
        float v = 0.f;
        if (s < 18) {
            int r = s >> 1, which = s & 1;           // 0 -> w0, 1 -> w2
            v = wm[c * 27 + r * 3 + (which ? 2 : 0)];
        } else if (s < 27) {
            int r = s - 18;
            v = wm[c * 27 + r * 3 + 1];              // w1
        }
        float* sf = (float*)d_scratch;
        sf[i * 2 + 0] = v;
        sf[i * 2 + 1] = v;
    }
}

// F-taps one row: consume cached weight, immediately prefetch next channel's
#define TAPFP(R) { \
    ulonglong2 u = wF[R]; wF[R] = nxtF[R]; \
    F0 = ffma2(u.x, W[R][0], F0); F1 = ffma2(u.x, W[R][1], F1); \
    F2 = ffma2(u.x, W[R][2], F2); F3 = ffma2(u.x, W[R][3], F3); \
    F0 = ffma2(u.y, W[R][1], F0); F1 = ffma2(u.y, W[R][2], F1); \
    F2 = ffma2(u.y, W[R][3], F2); F3 = ffma2(u.y, W[R][4], F3); }

// E-taps one row with given w1 pair
#define TAPE_(R, WP) { \
    E0 = ffma2(WP, W[R][0], E0); E1 = ffma2(WP, W[R][1], E1); \
    E2 = ffma2(WP, W[R][2], E2); E3 = ffma2(WP, W[R][3], E3); \
    E4 = ffma2(WP, W[R][4], E4); }

// E weight slot J covers tap-rows RA (lo half) and RB (hi half)
#define TAPEP2(J, RA, RB) { \
    ulonglong2 v = wE[J]; wE[J] = nxtE[J]; \
    TAPE_(RA, v.x) TAPE_(RB, v.y) }
#define TAPEP1(J, RA) { \
    ulonglong2 v = wE[J]; wE[J] = nxtE[J]; \
    TAPE_(RA, v.x) }

#define CHLOOP(ROWADJ) { \
    ulonglong2 wF[9], wE[5]; \
    const ulonglong2* cw0 = (const ulonglong2*)c_wpair; \
    _Pragma("unroll") \
    for (int rr = 0; rr < 9; rr++) wF[rr] = cw0[rr]; \
    _Pragma("unroll") \
    for (int j = 0; j < 5; j++) wE[j] = cw0[9 + j]; \
    _Pragma("unroll 1") \
    for (int c = 0; c < 64; c++) { \
        const ulonglong2* nxtF = (const ulonglong2*)(c_wpair + (c + 1) * 28); \
        const ulonglong2* nxtE = nxtF + 9; \
        ull bp = sBase[c]; \
        ull F0 = aptr[c], F1 = bp, F2 = bp, F3 = dptr[c]; \
        ull E0 = 0ULL, E1 = 0ULL, E2 = 0ULL, E3 = 0ULL, E4 = 0ULL; \
        if (ROWADJ) { \
            float adj = rowc[c]; \
            float aL = adj + (isL ? cornL[c] : 0.f); \
            float aR = adj + (isR ? cornR[c] : 0.f); \
            ull adjp = pk(adj, adj); \
            F0 = fadd2(F0, pk(aL, adj)); F1 = fadd2(F1, adjp); \
            F2 = fadd2(F2, adjp);        F3 = fadd2(F3, pk(adj, aR)); \
        } \
        TAPFP(0) TAPFP(1) TAPFP(2) TAPFP(3) TAPFP(4) \
        TAPFP(5) TAPFP(6) TAPFP(7) TAPFP(8) \
        TAPEP2(0, 0, 1) TAPEP2(1, 2, 3) TAPEP2(2, 4, 5) \
        TAPEP2(3, 6, 7) TAPEP1(4, 8) \
        ulonglong2 r01, r23; \
        r01.x = fadd2(F0, cross(E0, E1)); \
        r01.y = fadd2(F1, cross(E1, E2)); \
        r23.x = fadd2(F2, cross(E2, E3)); \
        r23.y = fadd2(F3, cross(E3, E4)); \
        float* op = outp + (size_t)c * IMG; \
        *reinterpret_cast<ulonglong2*>(op)     = r01; \
        *reinterpret_cast<ulonglong2*>(op + 4) = r23; \
    } }

__global__ void __launch_bounds__(128, 2) conv_main(
    const float* __restrict__ x,   // [8,3,512,512]
    const float* __restrict__ ei,  // [8,192]
    const float* __restrict__ bm,  // [64]
    const float* __restrict__ we,  // [64,3,3,3]
    const float* __restrict__ be,  // [64]
    float* __restrict__ out)       // [8,64,512,512]
{
    __shared__ __align__(16) float xs[3][6][260];   // rows h0-1..h0+4, cols w0-1..w0+256
    __shared__ ull sBase[64], sBaseL[64], sBaseR[64];
    __shared__ float sCT[64], sCB[64], sTL[64], sTR[64], sBL[64], sBR[64];

    const int tid = threadIdx.x, lane = tid & 31, wid = tid >> 5;
    const int cx = blockIdx.x, ty = blockIdx.y, b = blockIdx.z;
    const int w0 = cx * 256, h0 = ty * 4;

    // ---- stage input patch (zero padded) ----
    for (int i = tid; i < 3 * 6 * 258; i += 128) {
        int ci = i / 1548;
        int rem = i - ci * 1548;
        int rr = rem / 258, j = rem - rr * 258;
        int gh = h0 - 1 + rr, gw = w0 - 1 + j;
        float v = 0.f;
        if ((unsigned)gh < 512u && (unsigned)gw < 512u)
            v = x[((b * 3 + ci) * HW + gh) * HW + gw];
        xs[ci][rr][j] = v;
    }

    // ---- per-channel extra-term scalars ----
    if (tid < 64) {
        int c = tid;
        float S = 0, rT = 0, rB = 0, kL = 0, kR = 0;
        float tTL = 0, tTR = 0, tBL = 0, tBR = 0;
        #pragma unroll
        for (int e = 0; e < 3; e++) {
            float v = __ldg(ei + b * 192 + c * 3 + e);
            const float* wq = we + (c * 3 + e) * 9;
            #pragma unroll
            for (int ky = 0; ky < 3; ky++) {
                #pragma unroll
                for (int kx = 0; kx < 3; kx++) {
                    float t = v * __ldg(wq + ky * 3 + kx);
                    S += t;
                    if (ky == 0) rT += t;
                    if (ky == 2) rB += t;
                    if (kx == 0) kL += t;
                    if (kx == 2) kR += t;
                    if (ky == 0 && kx == 0) tTL += t;
                    if (ky == 0 && kx == 2) tTR += t;
                    if (ky == 2 && kx == 0) tBL += t;
                    if (ky == 2 && kx == 2) tBR += t;
                }
            }
        }
        float base = __ldg(bm + c) + __ldg(be + c) + S;
        sBase[c]  = pk(base, base);
        sBaseL[c] = pk(base - kL, base);
        sBaseR[c] = pk(base, base - kR);
        sCT[c] = -rT; sCB[c] = -rB;
        sTL[c] = tTL; sTR[c] = tTR; sBL[c] = tBL; sBR[c] = tBR;
    }
    __syncthreads();

    // ---- build 9x5 register window of aligned pairs q0..q4 per (ci,dy) row ----
    ull W[9][5];
    #pragma unroll
    for (int ci = 0; ci < 3; ci++) {
        #pragma unroll
        for (int dy = 0; dy < 3; dy++) {
            const float* p = &xs[ci][wid + dy][lane * 8];
            ulonglong2 q01 = *reinterpret_cast<const ulonglong2*>(p);
            ulonglong2 q23 = *reinterpret_cast<const ulonglong2*>(p + 4);
            ull q4 = *reinterpret_cast<const ull*>(p + 8);
            int r = ci * 3 + dy;
            W[r][0] = q01.x; W[r][1] = q01.y; W[r][2] = q23.x;
            W[r][3] = q23.y; W[r][4] = q4;
        }
    }

    const int h = h0 + wid;
    const bool isL = (cx == 0) && (lane == 0);
    const bool isR = (cx == 1) && (lane == 31);
    const bool top = (h == 0), bot = (h == HW - 1);

    const ull* aptr = isL ? sBaseL : sBase;
    const ull* dptr = isR ? sBaseR : sBase;

    float* outp = out + (((size_t)b * 64) * HW + h) * HW + w0 + lane * 8;

    if (!(top | bot)) {
        const float* rowc = sCT;
        const float* cornL = sTL;
        const float* cornR = sTR;
        (void)rowc; (void)cornL; (void)cornR;
        CHLOOP(false)
    } else {
        const float* rowc  = top ? sCT : sCB;
        const float* cornL = top ? sTL : sBL;
        const float* cornR = top ? sTR : sBR;
        CHLOOP(true)
    }
}

extern "C" void kernel_launch(void* const* d_in, const int* in_sizes, int n_in,
                              void* d_out, int out_size)
{
    const float* x  = (const float*)d_in[0];
    const float* ei = (const float*)d_in[1];
    const float* wm = (const float*)d_in[2];
    const float* bm = (const float*)d_in[3];
    const float* we = (const float*)d_in[4];
    const float* be = (const float*)d_in[5];
    float* out = (float*)d_out;

    prep_weights<<<(64 * 28 + 255) / 256, 256>>>(wm);

    void* scratch_ptr = nullptr;
    cudaGetSymbolAddress(&scratch_ptr, d_scratch);
    cudaMemcpyToSymbolAsync(c_wpair, scratch_ptr, sizeof(ull) * 65 * 28, 0,
                            cudaMemcpyDeviceToDevice, 0);

    dim3 grid(2, 128, 8);   // 2 col-blocks x 128 row-blocks x 8 batches = 2048 CTAs
    conv_main<<<grid, 128>>>(x, ei, bm, we, be, out);
}

// round 12
// speedup vs baseline: 1.0317x; 1.0317x over previous
#include <cuda_runtime.h>

typedef unsigned long long ull;

#define HW 512
#define IMG (512 * 512)

// raw weight layout: 64 ch x 28 floats (27 taps + pad) = 112B/ch -> 7 LDC.128
__constant__ __align__(16) float c_w[64 * 28];
__device__ float d_scratch[64 * 28];

__device__ __forceinline__ ull pk(float lo, float hi) {
    ull r;
    asm("mov.b64 %0, {%1,%2};" : "=l"(r) : "f"(lo), "f"(hi));
    return r;
}
__device__ __forceinline__ ull ffma2(ull a, ull b, ull c) {
    ull d;
    asm("fma.rn.f32x2 %0, %1, %2, %3;" : "=l"(d) : "l"(a), "l"(b), "l"(c));
    return d;
}
__device__ __forceinline__ ull fadd2(ull a, ull b) {
    ull d;
    asm("add.rn.f32x2 %0, %1, %2;" : "=l"(d) : "l"(a), "l"(b));
    return d;
}
// (a.hi, b.lo)
__device__ __forceinline__ ull cross(ull a, ull b) {
    ull r;
    asm("{\n\t"
        ".reg .b32 al, ah, bl, bh;\n\t"
        "mov.b64 {al, ah}, %1;\n\t"
        "mov.b64 {bl, bh}, %2;\n\t"
        "mov.b64 %0, {ah, bl};\n\t"
        "}" : "=l"(r) : "l"(a), "l"(b));
    return r;
}

__global__ void prep_weights(const float* __restrict__ wm) {
    int i = blockIdx.x * blockDim.x + threadIdx.x;   // over 64*28 slots
    if (i < 64 * 28) {
        int c = i / 28, s = i - c * 28;
        d_scratch[i] = (s < 27) ? wm[c * 27 + s] : 0.f;
    }
}

// one tap-row: build 3 (w,w) pairs from scalars (ALU), then 13 FFMA2
#define TAPROW(R) { \
    ull p0 = pk(wv[3*(R)],   wv[3*(R)]); \
    ull p2 = pk(wv[3*(R)+2], wv[3*(R)+2]); \
    F0 = ffma2(p0, W[R][0], F0); F1 = ffma2(p0, W[R][1], F1); \
    F2 = ffma2(p0, W[R][2], F2); F3 = ffma2(p0, W[R][3], F3); \
    F0 = ffma2(p2, W[R][1], F0); F1 = ffma2(p2, W[R][2], F1); \
    F2 = ffma2(p2, W[R][3], F2); F3 = ffma2(p2, W[R][4], F3); \
    ull p1 = pk(wv[3*(R)+1], wv[3*(R)+1]); \
    E0 = ffma2(p1, W[R][0], E0); E1 = ffma2(p1, W[R][1], E1); \
    E2 = ffma2(p1, W[R][2], E2); E3 = ffma2(p1, W[R][3], E3); \
    E4 = ffma2(p1, W[R][4], E4); }

#define CHLOOP(ROWADJ) \
    _Pragma("unroll 1") \
    for (int c = 0; c < 64; c++) { \
        const float4* cw4 = (const float4*)(c_w + c * 28); \
        float4 q0 = cw4[0], q1 = cw4[1], q2 = cw4[2], q3 = cw4[3]; \
        float4 q4 = cw4[4], q5 = cw4[5], q6 = cw4[6]; \
        float wv[28]; \
        wv[0]=q0.x;  wv[1]=q0.y;  wv[2]=q0.z;  wv[3]=q0.w; \
        wv[4]=q1.x;  wv[5]=q1.y;  wv[6]=q1.z;  wv[7]=q1.w; \
        wv[8]=q2.x;  wv[9]=q2.y;  wv[10]=q2.z; wv[11]=q2.w; \
        wv[12]=q3.x; wv[13]=q3.y; wv[14]=q3.z; wv[15]=q3.w; \
        wv[16]=q4.x; wv[17]=q4.y; wv[18]=q4.z; wv[19]=q4.w; \
        wv[20]=q5.x; wv[21]=q5.y; wv[22]=q5.z; wv[23]=q5.w; \
        wv[24]=q6.x; wv[25]=q6.y; wv[26]=q6.z; wv[27]=q6.w; \
        ull bp = sBase[c]; \
        ull F0 = aptr[c], F1 = bp, F2 = bp, F3 = dptr[c]; \
        ull E0 = 0ULL, E1 = 0ULL, E2 = 0ULL, E3 = 0ULL, E4 = 0ULL; \
        if (ROWADJ) { \
            float adj = rowc[c]; \
            float aL = adj + (isL ? cornL[c] : 0.f); \
            float aR = adj + (isR ? cornR[c] : 0.f); \
            ull adjp = pk(adj, adj); \
            F0 = fadd2(F0, pk(aL, adj)); F1 = fadd2(F1, adjp); \
            F2 = fadd2(F2, adjp);        F3 = fadd2(F3, pk(adj, aR)); \
        } \
        TAPROW(0) TAPROW(1) TAPROW(2) TAPROW(3) TAPROW(4) \
        TAPROW(5) TAPROW(6) TAPROW(7) TAPROW(8) \
        ulonglong2 r01, r23; \
        r01.x = fadd2(F0, cross(E0, E1)); \
        r01.y = fadd2(F1, cross(E1, E2)); \
        r23.x = fadd2(F2, cross(E2, E3)); \
        r23.y = fadd2(F3, cross(E3, E4)); \
        float* op = outp + (size_t)c * IMG; \
        *reinterpret_cast<ulonglong2*>(op)     = r01; \
        *reinterpret_cast<ulonglong2*>(op + 4) = r23; \
    }

__global__ void __launch_bounds__(128, 4) conv_main(
    const float* __restrict__ x,   // [8,3,512,512]
    const float* __restrict__ ei,  // [8,192]
    const float* __restrict__ bm,  // [64]
    const float* __restrict__ we,  // [64,3,3,3]
    const float* __restrict__ be,  // [64]
    float* __restrict__ out)       // [8,64,512,512]
{
    __shared__ __align__(16) float xs[3][6][260];   // rows h0-1..h0+4, cols w0-1..w0+256
    __shared__ ull sBase[64], sBaseL[64], sBaseR[64];
    __shared__ float sCT[64], sCB[64], sTL[64], sTR[64], sBL[64], sBR[64];

    const int tid = threadIdx.x, lane = tid & 31, wid = tid >> 5;
    const int cx = blockIdx.x, ty = blockIdx.y, b = blockIdx.z;
    const int w0 = cx * 256, h0 = ty * 4;

    // ---- stage input patch (zero padded) ----
    for (int i = tid; i < 3 * 6 * 258; i += 128) {
        int ci = i / 1548;
        int rem = i - ci * 1548;
        int rr = rem / 258, j = rem - rr * 258;
        int gh = h0 - 1 + rr, gw = w0 - 1 + j;
        float v = 0.f;
        if ((unsigned)gh < 512u && (unsigned)gw < 512u)
            v = x[((b * 3 + ci) * HW + gh) * HW + gw];
        xs[ci][rr][j] = v;
    }

    // ---- per-channel extra-term scalars ----
    if (tid < 64) {
        int c = tid;
        float S = 0, rT = 0, rB = 0, kL = 0, kR = 0;
        float tTL = 0, tTR = 0, tBL = 0, tBR = 0;
        #pragma unroll
        for (int e = 0; e < 3; e++) {
            float v = __ldg(ei + b * 192 + c * 3 + e);
            const float* wq = we + (c * 3 + e) * 9;
            #pragma unroll
            for (int ky = 0; ky < 3; ky++) {
                #pragma unroll
                for (int kx = 0; kx < 3; kx++) {
                    float t = v * __ldg(wq + ky * 3 + kx);
                    S += t;
                    if (ky == 0) rT += t;
                    if (ky == 2) rB += t;
                    if (kx == 0) kL += t;
                    if (kx == 2) kR += t;
                    if (ky == 0 && kx == 0) tTL += t;
                    if (ky == 0 && kx == 2) tTR += t;
                    if (ky == 2 && kx == 0) tBL += t;
                    if (ky == 2 && kx == 2) tBR += t;
                }
            }
        }
        float base = __ldg(bm + c) + __ldg(be + c) + S;
        sBase[c]  = pk(base, base);
        sBaseL[c] = pk(base - kL, base);
        sBaseR[c] = pk(base, base - kR);
        sCT[c] = -rT; sCB[c] = -rB;
        sTL[c] = tTL; sTR[c] = tTR; sBL[c] = tBL; sBR[c] = tBR;
    }
    __syncthreads();

    // ---- build 9x5 register window of aligned pairs q0..q4 per (ci,dy) row ----
    ull W[9][5];
    #pragma unroll
    for (int ci = 0; ci < 3; ci++) {
        #pragma unroll
        for (int dy = 0; dy < 3; dy++) {
            const float* p = &xs[ci][wid + dy][lane * 8];
            ulonglong2 q01 = *reinterpret_cast<const ulonglong2*>(p);
            ulonglong2 q23 = *reinterpret_cast<const ulonglong2*>(p + 4);
            ull q4 = *reinterpret_cast<const ull*>(p + 8);
            int r = ci * 3 + dy;
            W[r][0] = q01.x; W[r][1] = q01.y; W[r][2] = q23.x;
            W[r][3] = q23.y; W[r][4] = q4;
        }
    }

    const int h = h0 + wid;
    const bool isL = (cx == 0) && (lane == 0);
    const bool isR = (cx == 1) && (lane == 31);
    const bool top = (h == 0), bot = (h == HW - 1);

    const ull* aptr = isL ? sBaseL : sBase;
    const ull* dptr = isR ? sBaseR : sBase;

    float* outp = out + (((size_t)b * 64) * HW + h) * HW + w0 + lane * 8;

    if (!(top | bot)) {
        const float* rowc = sCT;
        const float* cornL = sTL;
        const float* cornR = sTR;
        (void)rowc; (void)cornL; (void)cornR;
        CHLOOP(false)
    } else {
        const float* rowc  = top ? sCT : sCB;
        const float* cornL = top ? sTL : sBL;
        const float* cornR = top ? sTR : sBR;
        CHLOOP(true)
    }
}

extern "C" void kernel_launch(void* const* d_in, const int* in_sizes, int n_in,
                              void* d_out, int out_size)
{
    const float* x  = (const float*)d_in[0];
    const float* ei = (const float*)d_in[1];
    const float* wm = (const float*)d_in[2];
    const float* bm = (const float*)d_in[3];
    const float* we = (const float*)d_in[4];
    const float* be = (const float*)d_in[5];
    float* out = (float*)d_out;

    prep_weights<<<(64 * 28 + 255) / 256, 256>>>(wm);

    void* scratch_ptr = nullptr;
    cudaGetSymbolAddress(&scratch_ptr, d_scratch);
    cudaMemcpyToSymbolAsync(c_w, scratch_ptr, sizeof(float) * 64 * 28, 0,
                            cudaMemcpyDeviceToDevice, 0);

    dim3 grid(2, 128, 8);   // 2 col-blocks x 128 row-blocks x 8 batches = 2048 CTAs
    conv_main<<<grid, 128>>>(x, ei, bm, we, be, out);
}